// round 1
// baseline (speedup 1.0000x reference)
#include <cuda_runtime.h>
#include <math.h>

#define B_  16
#define C_  512
#define HW_ 1024
#define C3_ 1536
#define NH_ 8
#define HC_ 64

// Scratch (device globals; allocation-free rule)
static __device__ float g_norm[(size_t)2 * B_ * C_ * HW_];    // normalized img|wm
static __device__ float g_t   [(size_t)2 * B_ * C3_ * HW_];   // pointwise conv out
static __device__ float g_qkv [(size_t)2 * B_ * C3_ * HW_];   // depthwise conv out
static __device__ float g_attn[(size_t)B_ * 2 * C_ * HW_];    // attention out (concat layout)
static __device__ float g_stats[2 * B_ * 2];                  // per-sample mean, rstd

// ---------------------------------------------------------------------------
// Kernel 1: per-sample LayerNorm statistics over [C,H,W] (524288 elems)
// ---------------------------------------------------------------------------
__global__ void ln_stats(const float* __restrict__ img, const float* __restrict__ wm) {
    int blk = blockIdx.x;            // 0..31 : s*16 + b
    int s = blk >> 4, b = blk & 15;
    const float* x = (s ? wm : img) + (size_t)b * C_ * HW_;
    float sum = 0.f, sq = 0.f;
    for (int i = threadIdx.x; i < C_ * HW_; i += blockDim.x) {
        float v = x[i];
        sum += v; sq += v * v;
    }
    __shared__ float s1[512], s2[512];
    s1[threadIdx.x] = sum; s2[threadIdx.x] = sq;
    __syncthreads();
    for (int st = 256; st > 0; st >>= 1) {
        if (threadIdx.x < st) {
            s1[threadIdx.x] += s1[threadIdx.x + st];
            s2[threadIdx.x] += s2[threadIdx.x + st];
        }
        __syncthreads();
    }
    if (threadIdx.x == 0) {
        float inv_n = 1.f / (float)(C_ * HW_);
        float mu  = s1[0] * inv_n;
        float var = s2[0] * inv_n - mu * mu;
        g_stats[blk * 2 + 0] = mu;
        g_stats[blk * 2 + 1] = rsqrtf(var + 1e-5f);
    }
}

// ---------------------------------------------------------------------------
// Kernel 2: apply LN affine (weights/biases indexed by chw)
// ---------------------------------------------------------------------------
__global__ void ln_apply(const float* __restrict__ img, const float* __restrict__ wm,
                         const float* __restrict__ iw, const float* __restrict__ ib,
                         const float* __restrict__ ww, const float* __restrict__ wb) {
    size_t idx = (size_t)blockIdx.x * blockDim.x + threadIdx.x;
    const size_t half = (size_t)B_ * C_ * HW_;
    if (idx >= 2 * half) return;
    int s = idx >= half;
    size_t r = idx - (size_t)s * half;
    int b = (int)(r / ((size_t)C_ * HW_));
    int chw = (int)(r % ((size_t)C_ * HW_));
    const float* x  = s ? wm : img;
    const float* w  = s ? ww : iw;
    const float* bb = s ? wb : ib;
    float mu   = g_stats[(s * 16 + b) * 2 + 0];
    float rstd = g_stats[(s * 16 + b) * 2 + 1];
    g_norm[idx] = (x[(size_t)b * C_ * HW_ + chw] - mu) * rstd * w[chw] + bb[chw];
}

// ---------------------------------------------------------------------------
// Kernel 3/6: tiled SGEMM  C[m][n] = sum_k Aop[m][k]*B[k][n] (+bias[m])
//   TA=false: A row-major [M][K];  TA=true: A stored [K][M] (transposed use)
//   Block tile 64x64, K-tile 16, 256 threads, 4x4 register microtiles.
// ---------------------------------------------------------------------------
template <bool TA>
__global__ void gemm64(const float* __restrict__ A, const float* __restrict__ Bm,
                       float* __restrict__ Cm, const float* __restrict__ bias,
                       int M, int N, int K, size_t strideB, size_t strideC) {
    __shared__ float As[16][64];
    __shared__ float Bs[16][64];
    const float* Bb = Bm + (size_t)blockIdx.z * strideB;
    float* Cb = Cm + (size_t)blockIdx.z * strideC;
    int m0 = blockIdx.y * 64, n0 = blockIdx.x * 64;
    int tid = threadIdx.x;
    float acc[4][4] = {};
    for (int k0 = 0; k0 < K; k0 += 16) {
        if (TA) {
            int kl = tid / 16, m4 = (tid % 16) * 4;
            float4 v = *(const float4*)&A[(size_t)(k0 + kl) * M + m0 + m4];
            As[kl][m4 + 0] = v.x; As[kl][m4 + 1] = v.y;
            As[kl][m4 + 2] = v.z; As[kl][m4 + 3] = v.w;
        } else {
            int ml = tid / 4, k4 = (tid % 4) * 4;
            float4 v = *(const float4*)&A[(size_t)(m0 + ml) * K + k0 + k4];
            As[k4 + 0][ml] = v.x; As[k4 + 1][ml] = v.y;
            As[k4 + 2][ml] = v.z; As[k4 + 3][ml] = v.w;
        }
        {
            int kl = tid / 16, n4 = (tid % 16) * 4;
            float4 v = *(const float4*)&Bb[(size_t)(k0 + kl) * N + n0 + n4];
            *(float4*)&Bs[kl][n4] = v;
        }
        __syncthreads();
        int ty = tid / 16, tx = tid % 16;
#pragma unroll
        for (int kk = 0; kk < 16; kk++) {
            float4 av = *(const float4*)&As[kk][ty * 4];
            float4 bv = *(const float4*)&Bs[kk][tx * 4];
            float a[4] = {av.x, av.y, av.z, av.w};
            float b[4] = {bv.x, bv.y, bv.z, bv.w};
#pragma unroll
            for (int i = 0; i < 4; i++)
#pragma unroll
                for (int j = 0; j < 4; j++)
                    acc[i][j] += a[i] * b[j];
        }
        __syncthreads();
    }
    int ty = tid / 16, tx = tid % 16;
#pragma unroll
    for (int i = 0; i < 4; i++) {
        int m = m0 + ty * 4 + i;
        float bv = bias ? bias[m] : 0.f;
#pragma unroll
        for (int j = 0; j < 4; j++)
            Cb[(size_t)m * N + n0 + tx * 4 + j] = acc[i][j] + bv;
    }
}

// ---------------------------------------------------------------------------
// Kernel 4: grouped 3x3 conv (groups = C, 3 in / 3 out channels per group)
//   in = g_t, out = g_qkv
// ---------------------------------------------------------------------------
__global__ void dwconv_kernel(const float* __restrict__ wimg, const float* __restrict__ bimg,
                              const float* __restrict__ wwm,  const float* __restrict__ bwm) {
    size_t idx = (size_t)blockIdx.x * blockDim.x + threadIdx.x;
    const size_t half = (size_t)B_ * C3_ * HW_;
    if (idx >= 2 * half) return;
    int s = idx >= half;
    size_t r = idx - (size_t)s * half;
    int b  = (int)(r / ((size_t)C3_ * HW_));
    int rr = (int)(r % ((size_t)C3_ * HW_));
    int o = rr / HW_, hw = rr % HW_;
    int y = hw >> 5, x = hw & 31;
    const float* w  = (s ? wwm : wimg) + (size_t)o * 27;
    const float* in = g_t + ((size_t)(s * B_ + b) * C3_ + (o / 3) * 3) * HW_;
    float acc = (s ? bwm : bimg)[o];
#pragma unroll
    for (int i = 0; i < 3; i++)
#pragma unroll
        for (int ky = 0; ky < 3; ky++) {
            int yy = y + ky - 1;
            if (yy < 0 || yy >= 32) continue;
#pragma unroll
            for (int kx = 0; kx < 3; kx++) {
                int xx = x + kx - 1;
                if (xx < 0 || xx >= 32) continue;
                acc += w[i * 9 + ky * 3 + kx] * in[(size_t)i * HW_ + yy * 32 + xx];
            }
        }
    g_qkv[idx] = acc;
}

// ---------------------------------------------------------------------------
// Kernel 5: cross-attention per (b, head, stream). 512 threads/block.
//   S[k][q] = sum_p Kc[k][p]*Q[q][p]   (k<128, q<64, p<1024)
//   softmax over q, then out[q][p] = sum_k S[k][q]*Vc[k][p]
//   Output layout matches concat: g_attn[b][n*128 + s*64 + q][p]
// ---------------------------------------------------------------------------
__global__ void attn_kernel() {
    __shared__ float sm[12288];   // 48 KB union
    int bid = blockIdx.x;
    int s = bid & 1, n = (bid >> 1) & 7, b = bid >> 4;
    int tid = threadIdx.x;
    const size_t SB = (size_t)B_ * C3_ * HW_;
    const float* qbase  = g_qkv + (s ? SB : 0) + ((size_t)b * C3_ + n * HC_) * HW_;
    const float* k0base = g_qkv + ((size_t)b * C3_ + C_ + n * HC_) * HW_;
    const float* k1base = k0base + SB;
    const float* v0base = g_qkv + ((size_t)b * C3_ + 2 * C_ + n * HC_) * HW_;
    const float* v1base = v0base + SB;

    int q = tid & 63, kg = tid >> 6;   // q in [0,64), kg in [0,8) -> 16 k-rows each
    float acc[16];
#pragma unroll
    for (int i = 0; i < 16; i++) acc[i] = 0.f;

    float* Ks = sm;          // [128][32]
    float* Qs = sm + 4096;   // [32][65] padded (conflict-free transpose)

    for (int pc = 0; pc < 32; pc++) {
        __syncthreads();
#pragma unroll
        for (int i = 0; i < 8; i++) {
            int idx = tid + i * 512;
            int k = idx >> 5, p = idx & 31;
            const float* kr = (k < 64) ? k0base + (size_t)k * HW_
                                       : k1base + (size_t)(k - 64) * HW_;
            Ks[idx] = kr[pc * 32 + p];
        }
#pragma unroll
        for (int i = 0; i < 4; i++) {
            int idx = tid + i * 512;
            int qq = idx >> 5, p = idx & 31;
            Qs[p * 65 + qq] = qbase[(size_t)qq * HW_ + pc * 32 + p];
        }
        __syncthreads();
#pragma unroll 4
        for (int p = 0; p < 32; p++) {
            float qv = Qs[p * 65 + q];
#pragma unroll
            for (int kk = 0; kk < 16; kk++)
                acc[kk] += Ks[(kg * 16 + kk) * 32 + p] * qv;
        }
    }
    __syncthreads();
    float* S = sm;           // [128][64]
#pragma unroll
    for (int kk = 0; kk < 16; kk++)
        S[(kg * 16 + kk) * 64 + q] = acc[kk];
    __syncthreads();
    if (tid < 128) {         // softmax over q per k-row
        float mx = -1e30f;
        for (int j = 0; j < 64; j++) mx = fmaxf(mx, S[tid * 64 + j]);
        float sum = 0.f;
        for (int j = 0; j < 64; j++) {
            float e = expf(S[tid * 64 + j] - mx);
            S[tid * 64 + j] = e; sum += e;
        }
        float inv = 1.f / sum;
        for (int j = 0; j < 64; j++) S[tid * 64 + j] *= inv;
    }

    float* Vs = sm + 8192;   // [128][32]
    int pl = tid & 31, q0 = (tid >> 5) * 4;
    float* outbase = g_attn + ((size_t)b * (2 * C_) + n * 128 + s * 64) * HW_;
    for (int pc = 0; pc < 32; pc++) {
        __syncthreads();
#pragma unroll
        for (int i = 0; i < 8; i++) {
            int idx = tid + i * 512;
            int k = idx >> 5, p = idx & 31;
            const float* vr = (k < 64) ? v0base + (size_t)k * HW_
                                       : v1base + (size_t)(k - 64) * HW_;
            Vs[idx] = vr[pc * 32 + p];
        }
        __syncthreads();
        float a0 = 0, a1 = 0, a2 = 0, a3 = 0;
#pragma unroll 8
        for (int k = 0; k < 128; k++) {
            float4 sv = *(const float4*)&S[k * 64 + q0];
            float vv = Vs[k * 32 + pl];
            a0 += sv.x * vv; a1 += sv.y * vv;
            a2 += sv.z * vv; a3 += sv.w * vv;
        }
        outbase[(size_t)(q0 + 0) * HW_ + pc * 32 + pl] = a0;
        outbase[(size_t)(q0 + 1) * HW_ + pc * 32 + pl] = a1;
        outbase[(size_t)(q0 + 2) * HW_ + pc * 32 + pl] = a2;
        outbase[(size_t)(q0 + 3) * HW_ + pc * 32 + pl] = a3;
    }
}

// ---------------------------------------------------------------------------
extern "C" void kernel_launch(void* const* d_in, const int* in_sizes, int n_in,
                              void* d_out, int out_size) {
    const float* image     = (const float*)d_in[0];
    const float* watermark = (const float*)d_in[1];
    const float* img_ln_w  = (const float*)d_in[2];
    const float* img_ln_b  = (const float*)d_in[3];
    const float* wm_ln_w   = (const float*)d_in[4];
    const float* wm_ln_b   = (const float*)d_in[5];
    const float* img_pw_w  = (const float*)d_in[6];
    const float* img_pw_b  = (const float*)d_in[7];
    const float* img_dw_w  = (const float*)d_in[8];
    const float* img_dw_b  = (const float*)d_in[9];
    const float* wm_pw_w   = (const float*)d_in[10];
    const float* wm_pw_b   = (const float*)d_in[11];
    const float* wm_dw_w   = (const float*)d_in[12];
    const float* wm_dw_b   = (const float*)d_in[13];
    const float* proj      = (const float*)d_in[14];
    float* out = (float*)d_out;

    float *p_norm, *p_t, *p_attn;
    cudaGetSymbolAddress((void**)&p_norm, g_norm);
    cudaGetSymbolAddress((void**)&p_t,    g_t);
    cudaGetSymbolAddress((void**)&p_attn, g_attn);

    // 1) LayerNorm
    ln_stats<<<32, 512>>>(image, watermark);
    size_t totalN = (size_t)2 * B_ * C_ * HW_;
    ln_apply<<<(unsigned)((totalN + 255) / 256), 256>>>(
        image, watermark, img_ln_w, img_ln_b, wm_ln_w, wm_ln_b);

    // 2) Pointwise 1x1 conv (GEMM), per stream
    dim3 gpw(HW_ / 64, C3_ / 64, B_);
    gemm64<false><<<gpw, 256>>>(img_pw_w, p_norm, p_t, img_pw_b,
                                C3_, HW_, C_, (size_t)C_ * HW_, (size_t)C3_ * HW_);
    gemm64<false><<<gpw, 256>>>(wm_pw_w, p_norm + (size_t)B_ * C_ * HW_,
                                p_t + (size_t)B_ * C3_ * HW_, wm_pw_b,
                                C3_, HW_, C_, (size_t)C_ * HW_, (size_t)C3_ * HW_);

    // 3) Grouped 3x3 conv
    size_t totalD = (size_t)2 * B_ * C3_ * HW_;
    dwconv_kernel<<<(unsigned)((totalD + 255) / 256), 256>>>(
        img_dw_w, img_dw_b, wm_dw_w, wm_dw_b);

    // 4) Cross-attention (B*NH*2 blocks)
    attn_kernel<<<B_ * NH_ * 2, 512>>>();

    // 5) Final projection GEMM (A = proj stored [2C][C] -> transposed use)
    dim3 gf(HW_ / 64, C_ / 64, B_);
    gemm64<true><<<gf, 256>>>(proj, p_attn, out, nullptr,
                              C_, HW_, 2 * C_, (size_t)2 * C_ * HW_, (size_t)C_ * HW_);
}

// round 2
// speedup vs baseline: 1.8471x; 1.8471x over previous
#include <cuda_runtime.h>
#include <math.h>

#define B_  16
#define C_  512
#define HW_ 1024
#define C3_ 1536
#define NH_ 8
#define HC_ 64

// Scratch (device globals; allocation-free rule)
static __device__ float g_norm[(size_t)2 * B_ * C_ * HW_];    // normalized img|wm
static __device__ float g_t   [(size_t)2 * B_ * C3_ * HW_];   // pointwise conv out
static __device__ float g_qkv [(size_t)2 * B_ * C3_ * HW_];   // depthwise conv out
static __device__ float g_attn[(size_t)B_ * 2 * C_ * HW_];    // attention out (concat layout)
static __device__ float g_stats[2 * B_ * 2];                  // per-sample mean, rstd

// ---------------------------------------------------------------------------
// Kernel 1: per-sample LayerNorm statistics over [C,H,W]
// ---------------------------------------------------------------------------
__global__ void ln_stats(const float* __restrict__ img, const float* __restrict__ wm) {
    int blk = blockIdx.x;            // 0..31 : s*16 + b
    int s = blk >> 4, b = blk & 15;
    const float* x = (s ? wm : img) + (size_t)b * C_ * HW_;
    float sum = 0.f, sq = 0.f;
    for (int i = threadIdx.x; i < C_ * HW_; i += blockDim.x) {
        float v = x[i];
        sum += v; sq += v * v;
    }
    __shared__ float s1[512], s2[512];
    s1[threadIdx.x] = sum; s2[threadIdx.x] = sq;
    __syncthreads();
    for (int st = 256; st > 0; st >>= 1) {
        if (threadIdx.x < st) {
            s1[threadIdx.x] += s1[threadIdx.x + st];
            s2[threadIdx.x] += s2[threadIdx.x + st];
        }
        __syncthreads();
    }
    if (threadIdx.x == 0) {
        float inv_n = 1.f / (float)(C_ * HW_);
        float mu  = s1[0] * inv_n;
        float var = s2[0] * inv_n - mu * mu;
        g_stats[blk * 2 + 0] = mu;
        g_stats[blk * 2 + 1] = rsqrtf(var + 1e-5f);
    }
}

// ---------------------------------------------------------------------------
// Kernel 2: apply LN affine
// ---------------------------------------------------------------------------
__global__ void ln_apply(const float* __restrict__ img, const float* __restrict__ wm,
                         const float* __restrict__ iw, const float* __restrict__ ib,
                         const float* __restrict__ ww, const float* __restrict__ wb) {
    size_t idx = (size_t)blockIdx.x * blockDim.x + threadIdx.x;
    const size_t half = (size_t)B_ * C_ * HW_;
    if (idx >= 2 * half) return;
    int s = idx >= half;
    size_t r = idx - (size_t)s * half;
    int b = (int)(r / ((size_t)C_ * HW_));
    int chw = (int)(r % ((size_t)C_ * HW_));
    const float* x  = s ? wm : img;
    const float* w  = s ? ww : iw;
    const float* bb = s ? wb : ib;
    float mu   = g_stats[(s * 16 + b) * 2 + 0];
    float rstd = g_stats[(s * 16 + b) * 2 + 1];
    g_norm[idx] = (x[(size_t)b * C_ * HW_ + chw] - mu) * rstd * w[chw] + bb[chw];
}

// ---------------------------------------------------------------------------
// tf32 helpers
// ---------------------------------------------------------------------------
__device__ __forceinline__ unsigned f2tf32(float f) {
    unsigned r; asm("cvt.rna.tf32.f32 %0, %1;" : "=r"(r) : "f"(f)); return r;
}
__device__ __forceinline__ void mma_tf32(float* c, const unsigned* a, const unsigned* b) {
    asm volatile(
        "mma.sync.aligned.m16n8k8.row.col.f32.tf32.tf32.f32 "
        "{%0,%1,%2,%3}, {%4,%5,%6,%7}, {%8,%9}, {%0,%1,%2,%3};"
        : "+f"(c[0]), "+f"(c[1]), "+f"(c[2]), "+f"(c[3])
        : "r"(a[0]), "r"(a[1]), "r"(a[2]), "r"(a[3]), "r"(b[0]), "r"(b[1]));
}

// ---------------------------------------------------------------------------
// Kernel 3/6: tf32 tensor-core GEMM. Block tile 128x128, kTile 16, 256 threads,
// 8 warps (4 M x 2 N), warp tile 32x64, mma m16n8k8, double-buffered smem.
//   TA=false: A row-major [M][K];  TA=true: A stored [K][M].
// ---------------------------------------------------------------------------
template <bool TA>
__global__ __launch_bounds__(256)
void gemm_tc(const float* __restrict__ A, const float* __restrict__ Bm,
             float* __restrict__ Cm, const float* __restrict__ bias,
             int M, int N, int K, size_t strideB, size_t strideC) {
    __shared__ unsigned As[2][16][132];
    __shared__ unsigned Bs[2][16][132];
    const float* Bb = Bm + (size_t)blockIdx.z * strideB;
    float* Cb = Cm + (size_t)blockIdx.z * strideC;
    int m0 = blockIdx.y * 128, n0 = blockIdx.x * 128;
    int tid = threadIdx.x, lane = tid & 31, wid = tid >> 5;
    int warpM = wid & 3, warpN = wid >> 2;
    int gi = lane >> 2, li = lane & 3;

    float acc[2][8][4];
#pragma unroll
    for (int mi = 0; mi < 2; mi++)
#pragma unroll
        for (int ni = 0; ni < 8; ni++)
#pragma unroll
            for (int j = 0; j < 4; j++) acc[mi][ni][j] = 0.f;

    const int T = K / 16;
    float4 sa[2], sb[2];

    // ---- fetch tile 0 ----
    {
        int k0 = 0;
#pragma unroll
        for (int r = 0; r < 2; r++) {
            int idx = tid + r * 256;
            if (TA) {
                int kl = idx >> 5, mq = idx & 31;
                sa[r] = *(const float4*)&A[(size_t)(k0 + kl) * M + m0 + mq * 4];
            } else {
                int ml = idx >> 2, kq = idx & 3;
                sa[r] = *(const float4*)&A[(size_t)(m0 + ml) * K + k0 + kq * 4];
            }
            int kl = idx >> 5, nq = idx & 31;
            sb[r] = *(const float4*)&Bb[(size_t)(k0 + kl) * N + n0 + nq * 4];
        }
    }
    // ---- store tile 0 into buf 0 ----
#pragma unroll
    for (int r = 0; r < 2; r++) {
        int idx = tid + r * 256;
        if (TA) {
            int kl = idx >> 5, mq = idx & 31;
            uint4 u = {f2tf32(sa[r].x), f2tf32(sa[r].y), f2tf32(sa[r].z), f2tf32(sa[r].w)};
            *(uint4*)&As[0][kl][mq * 4] = u;
        } else {
            int ml = idx >> 2, kq = idx & 3;
            As[0][kq * 4 + 0][ml] = f2tf32(sa[r].x);
            As[0][kq * 4 + 1][ml] = f2tf32(sa[r].y);
            As[0][kq * 4 + 2][ml] = f2tf32(sa[r].z);
            As[0][kq * 4 + 3][ml] = f2tf32(sa[r].w);
        }
        int kl = idx >> 5, nq = idx & 31;
        uint4 u = {f2tf32(sb[r].x), f2tf32(sb[r].y), f2tf32(sb[r].z), f2tf32(sb[r].w)};
        *(uint4*)&Bs[0][kl][nq * 4] = u;
    }
    __syncthreads();

    for (int t = 0; t < T; t++) {
        int buf = t & 1;
        // prefetch next tile into regs
        if (t + 1 < T) {
            int k0 = (t + 1) * 16;
#pragma unroll
            for (int r = 0; r < 2; r++) {
                int idx = tid + r * 256;
                if (TA) {
                    int kl = idx >> 5, mq = idx & 31;
                    sa[r] = *(const float4*)&A[(size_t)(k0 + kl) * M + m0 + mq * 4];
                } else {
                    int ml = idx >> 2, kq = idx & 3;
                    sa[r] = *(const float4*)&A[(size_t)(m0 + ml) * K + k0 + kq * 4];
                }
                int kl = idx >> 5, nq = idx & 31;
                sb[r] = *(const float4*)&Bb[(size_t)(k0 + kl) * N + n0 + nq * 4];
            }
        }
        // compute on buf
#pragma unroll
        for (int ks = 0; ks < 2; ks++) {
            int k8 = ks * 8;
            unsigned a[2][4], b[8][2];
#pragma unroll
            for (int mi = 0; mi < 2; mi++) {
                int m = warpM * 32 + mi * 16 + gi;
                a[mi][0] = As[buf][k8 + li][m];
                a[mi][1] = As[buf][k8 + li][m + 8];
                a[mi][2] = As[buf][k8 + li + 4][m];
                a[mi][3] = As[buf][k8 + li + 4][m + 8];
            }
#pragma unroll
            for (int ni = 0; ni < 8; ni++) {
                int n = warpN * 64 + ni * 8 + gi;
                b[ni][0] = Bs[buf][k8 + li][n];
                b[ni][1] = Bs[buf][k8 + li + 4][n];
            }
#pragma unroll
            for (int mi = 0; mi < 2; mi++)
#pragma unroll
                for (int ni = 0; ni < 8; ni++)
                    mma_tf32(acc[mi][ni], a[mi], b[ni]);
        }
        // store prefetched tile into other buffer
        if (t + 1 < T) {
            int ob = buf ^ 1;
#pragma unroll
            for (int r = 0; r < 2; r++) {
                int idx = tid + r * 256;
                if (TA) {
                    int kl = idx >> 5, mq = idx & 31;
                    uint4 u = {f2tf32(sa[r].x), f2tf32(sa[r].y), f2tf32(sa[r].z), f2tf32(sa[r].w)};
                    *(uint4*)&As[ob][kl][mq * 4] = u;
                } else {
                    int ml = idx >> 2, kq = idx & 3;
                    As[ob][kq * 4 + 0][ml] = f2tf32(sa[r].x);
                    As[ob][kq * 4 + 1][ml] = f2tf32(sa[r].y);
                    As[ob][kq * 4 + 2][ml] = f2tf32(sa[r].z);
                    As[ob][kq * 4 + 3][ml] = f2tf32(sa[r].w);
                }
                int kl = idx >> 5, nq = idx & 31;
                uint4 u = {f2tf32(sb[r].x), f2tf32(sb[r].y), f2tf32(sb[r].z), f2tf32(sb[r].w)};
                *(uint4*)&Bs[ob][kl][nq * 4] = u;
            }
        }
        __syncthreads();
    }

    // ---- epilogue ----
#pragma unroll
    for (int mi = 0; mi < 2; mi++) {
        int mrow = m0 + warpM * 32 + mi * 16 + gi;
        float bv0 = bias ? bias[mrow] : 0.f;
        float bv1 = bias ? bias[mrow + 8] : 0.f;
#pragma unroll
        for (int ni = 0; ni < 8; ni++) {
            int n = n0 + warpN * 64 + ni * 8 + 2 * li;
            float2 v0 = {acc[mi][ni][0] + bv0, acc[mi][ni][1] + bv0};
            float2 v1 = {acc[mi][ni][2] + bv1, acc[mi][ni][3] + bv1};
            *(float2*)&Cb[(size_t)mrow * N + n] = v0;
            *(float2*)&Cb[(size_t)(mrow + 8) * N + n] = v1;
        }
    }
}

// ---------------------------------------------------------------------------
// Kernel 4: grouped 3x3 conv, smem-tiled: one block per (stream,sample,group)
// ---------------------------------------------------------------------------
__global__ __launch_bounds__(256)
void dwconv_kernel(const float* __restrict__ wimg, const float* __restrict__ bimg,
                   const float* __restrict__ wwm,  const float* __restrict__ bwm) {
    __shared__ float sin_[3][HW_];
    __shared__ float sw[81];
    __shared__ float sbias[3];
    int blk = blockIdx.x;                 // sb*512 + g
    int g = blk & 511, sb = blk >> 9;     // sb: s*16+b
    int s = sb >> 4;
    int tid = threadIdx.x;
    const float* in = g_t + ((size_t)sb * C3_ + g * 3) * HW_;
#pragma unroll
    for (int r = 0; r < 3; r++) {
        int idx = tid + r * 256;          // 768 float4 = 3*1024 floats
        ((float4*)sin_)[idx] = ((const float4*)in)[idx];
    }
    const float* w = (s ? wwm : wimg) + (size_t)g * 81;
    if (tid < 81) sw[tid] = w[tid];
    if (tid < 3) sbias[tid] = (s ? bwm : bimg)[g * 3 + tid];
    __syncthreads();
    float* outp = g_qkv + ((size_t)sb * C3_ + g * 3) * HW_;
#pragma unroll
    for (int o = 0; o < 3; o++) {
#pragma unroll
        for (int r = 0; r < 4; r++) {
            int hw = tid + r * 256;
            int y = hw >> 5, x = hw & 31;
            float accv = sbias[o];
#pragma unroll
            for (int i = 0; i < 3; i++)
#pragma unroll
                for (int ky = 0; ky < 3; ky++) {
                    int yy = y + ky - 1;
                    if (yy < 0 || yy >= 32) continue;
#pragma unroll
                    for (int kx = 0; kx < 3; kx++) {
                        int xx = x + kx - 1;
                        if (xx < 0 || xx >= 32) continue;
                        accv += sw[o * 27 + i * 9 + ky * 3 + kx] * sin_[i][yy * 32 + xx];
                    }
                }
            outp[(size_t)o * HW_ + hw] = accv;
        }
    }
}

// ---------------------------------------------------------------------------
// Kernel 5: cross-attention per (b, head, stream). 512 threads/block.
// ---------------------------------------------------------------------------
__global__ void attn_kernel() {
    __shared__ float sm[12288];   // 48 KB union
    int bid = blockIdx.x;
    int s = bid & 1, n = (bid >> 1) & 7, b = bid >> 4;
    int tid = threadIdx.x;
    const size_t SB = (size_t)B_ * C3_ * HW_;
    const float* qbase  = g_qkv + (s ? SB : 0) + ((size_t)b * C3_ + n * HC_) * HW_;
    const float* k0base = g_qkv + ((size_t)b * C3_ + C_ + n * HC_) * HW_;
    const float* k1base = k0base + SB;
    const float* v0base = g_qkv + ((size_t)b * C3_ + 2 * C_ + n * HC_) * HW_;
    const float* v1base = v0base + SB;

    int q = tid & 63, kg = tid >> 6;
    float acc[16];
#pragma unroll
    for (int i = 0; i < 16; i++) acc[i] = 0.f;

    float* Ks = sm;          // [128][32]
    float* Qs = sm + 4096;   // [32][65] padded

    for (int pc = 0; pc < 32; pc++) {
        __syncthreads();
#pragma unroll
        for (int i = 0; i < 8; i++) {
            int idx = tid + i * 512;
            int k = idx >> 5, p = idx & 31;
            const float* kr = (k < 64) ? k0base + (size_t)k * HW_
                                       : k1base + (size_t)(k - 64) * HW_;
            Ks[idx] = kr[pc * 32 + p];
        }
#pragma unroll
        for (int i = 0; i < 4; i++) {
            int idx = tid + i * 512;
            int qq = idx >> 5, p = idx & 31;
            Qs[p * 65 + qq] = qbase[(size_t)qq * HW_ + pc * 32 + p];
        }
        __syncthreads();
#pragma unroll 4
        for (int p = 0; p < 32; p++) {
            float qv = Qs[p * 65 + q];
#pragma unroll
            for (int kk = 0; kk < 16; kk++)
                acc[kk] += Ks[(kg * 16 + kk) * 32 + p] * qv;
        }
    }
    __syncthreads();
    float* S = sm;           // [128][64]
#pragma unroll
    for (int kk = 0; kk < 16; kk++)
        S[(kg * 16 + kk) * 64 + q] = acc[kk];
    __syncthreads();
    if (tid < 128) {
        float mx = -1e30f;
        for (int j = 0; j < 64; j++) mx = fmaxf(mx, S[tid * 64 + j]);
        float sum = 0.f;
        for (int j = 0; j < 64; j++) {
            float e = expf(S[tid * 64 + j] - mx);
            S[tid * 64 + j] = e; sum += e;
        }
        float inv = 1.f / sum;
        for (int j = 0; j < 64; j++) S[tid * 64 + j] *= inv;
    }

    float* Vs = sm + 8192;   // [128][32]
    int pl = tid & 31, q0 = (tid >> 5) * 4;
    float* outbase = g_attn + ((size_t)b * (2 * C_) + n * 128 + s * 64) * HW_;
    for (int pc = 0; pc < 32; pc++) {
        __syncthreads();
#pragma unroll
        for (int i = 0; i < 8; i++) {
            int idx = tid + i * 512;
            int k = idx >> 5, p = idx & 31;
            const float* vr = (k < 64) ? v0base + (size_t)k * HW_
                                       : v1base + (size_t)(k - 64) * HW_;
            Vs[idx] = vr[pc * 32 + p];
        }
        __syncthreads();
        float a0 = 0, a1 = 0, a2 = 0, a3 = 0;
#pragma unroll 8
        for (int k = 0; k < 128; k++) {
            float4 sv = *(const float4*)&S[k * 64 + q0];
            float vv = Vs[k * 32 + pl];
            a0 += sv.x * vv; a1 += sv.y * vv;
            a2 += sv.z * vv; a3 += sv.w * vv;
        }
        outbase[(size_t)(q0 + 0) * HW_ + pc * 32 + pl] = a0;
        outbase[(size_t)(q0 + 1) * HW_ + pc * 32 + pl] = a1;
        outbase[(size_t)(q0 + 2) * HW_ + pc * 32 + pl] = a2;
        outbase[(size_t)(q0 + 3) * HW_ + pc * 32 + pl] = a3;
    }
}

// ---------------------------------------------------------------------------
extern "C" void kernel_launch(void* const* d_in, const int* in_sizes, int n_in,
                              void* d_out, int out_size) {
    const float* image     = (const float*)d_in[0];
    const float* watermark = (const float*)d_in[1];
    const float* img_ln_w  = (const float*)d_in[2];
    const float* img_ln_b  = (const float*)d_in[3];
    const float* wm_ln_w   = (const float*)d_in[4];
    const float* wm_ln_b   = (const float*)d_in[5];
    const float* img_pw_w  = (const float*)d_in[6];
    const float* img_pw_b  = (const float*)d_in[7];
    const float* img_dw_w  = (const float*)d_in[8];
    const float* img_dw_b  = (const float*)d_in[9];
    const float* wm_pw_w   = (const float*)d_in[10];
    const float* wm_pw_b   = (const float*)d_in[11];
    const float* wm_dw_w   = (const float*)d_in[12];
    const float* wm_dw_b   = (const float*)d_in[13];
    const float* proj      = (const float*)d_in[14];
    float* out = (float*)d_out;

    float *p_norm, *p_t, *p_attn;
    cudaGetSymbolAddress((void**)&p_norm, g_norm);
    cudaGetSymbolAddress((void**)&p_t,    g_t);
    cudaGetSymbolAddress((void**)&p_attn, g_attn);

    // 1) LayerNorm
    ln_stats<<<32, 512>>>(image, watermark);
    size_t totalN = (size_t)2 * B_ * C_ * HW_;
    ln_apply<<<(unsigned)((totalN + 255) / 256), 256>>>(
        image, watermark, img_ln_w, img_ln_b, wm_ln_w, wm_ln_b);

    // 2) Pointwise 1x1 conv (tf32 tensor-core GEMM), per stream
    dim3 gpw(HW_ / 128, C3_ / 128, B_);
    gemm_tc<false><<<gpw, 256>>>(img_pw_w, p_norm, p_t, img_pw_b,
                                 C3_, HW_, C_, (size_t)C_ * HW_, (size_t)C3_ * HW_);
    gemm_tc<false><<<gpw, 256>>>(wm_pw_w, p_norm + (size_t)B_ * C_ * HW_,
                                 p_t + (size_t)B_ * C3_ * HW_, wm_pw_b,
                                 C3_, HW_, C_, (size_t)C_ * HW_, (size_t)C3_ * HW_);

    // 3) Grouped 3x3 conv (smem-tiled)
    dwconv_kernel<<<32 * 512, 256>>>(img_dw_w, img_dw_b, wm_dw_w, wm_dw_b);

    // 4) Cross-attention
    attn_kernel<<<B_ * NH_ * 2, 512>>>();

    // 5) Final projection GEMM (A = proj stored [2C][C] -> transposed use)
    dim3 gf(HW_ / 128, C_ / 128, B_);
    gemm_tc<true><<<gf, 256>>>(proj, p_attn, out, nullptr,
                               C_, HW_, 2 * C_, (size_t)2 * C_ * HW_, (size_t)C_ * HW_);
}

// round 3
// speedup vs baseline: 2.2044x; 1.1935x over previous
#include <cuda_runtime.h>
#include <math.h>

#define B_  16
#define C_  512
#define HW_ 1024
#define C3_ 1536
#define NH_ 8
#define HC_ 64

// Scratch (device globals; allocation-free rule)
static __device__ float g_norm[(size_t)2 * B_ * C_ * HW_];    // normalized img|wm
static __device__ float g_t   [(size_t)2 * B_ * C3_ * HW_];   // pointwise conv out
static __device__ float g_qkv [(size_t)2 * B_ * C3_ * HW_];   // depthwise conv out
static __device__ float g_attn[(size_t)B_ * 2 * C_ * HW_];    // attention out (concat layout)
static __device__ float g_stats[2 * B_ * 2];                  // per-sample mean, rstd

// ---------------------------------------------------------------------------
// Kernel 1: per-sample LayerNorm statistics over [C,H,W]
// ---------------------------------------------------------------------------
__global__ void ln_stats(const float* __restrict__ img, const float* __restrict__ wm) {
    int blk = blockIdx.x;            // 0..31 : s*16 + b
    int s = blk >> 4, b = blk & 15;
    const float* x = (s ? wm : img) + (size_t)b * C_ * HW_;
    float sum = 0.f, sq = 0.f;
    for (int i = threadIdx.x; i < C_ * HW_; i += blockDim.x) {
        float v = x[i];
        sum += v; sq += v * v;
    }
    __shared__ float s1[512], s2[512];
    s1[threadIdx.x] = sum; s2[threadIdx.x] = sq;
    __syncthreads();
    for (int st = 256; st > 0; st >>= 1) {
        if (threadIdx.x < st) {
            s1[threadIdx.x] += s1[threadIdx.x + st];
            s2[threadIdx.x] += s2[threadIdx.x + st];
        }
        __syncthreads();
    }
    if (threadIdx.x == 0) {
        float inv_n = 1.f / (float)(C_ * HW_);
        float mu  = s1[0] * inv_n;
        float var = s2[0] * inv_n - mu * mu;
        g_stats[blk * 2 + 0] = mu;
        g_stats[blk * 2 + 1] = rsqrtf(var + 1e-5f);
    }
}

// ---------------------------------------------------------------------------
// Kernel 2: apply LN affine
// ---------------------------------------------------------------------------
__global__ void ln_apply(const float* __restrict__ img, const float* __restrict__ wm,
                         const float* __restrict__ iw, const float* __restrict__ ib,
                         const float* __restrict__ ww, const float* __restrict__ wb) {
    size_t idx = (size_t)blockIdx.x * blockDim.x + threadIdx.x;
    const size_t half = (size_t)B_ * C_ * HW_;
    if (idx >= 2 * half) return;
    int s = idx >= half;
    size_t r = idx - (size_t)s * half;
    int b = (int)(r / ((size_t)C_ * HW_));
    int chw = (int)(r % ((size_t)C_ * HW_));
    const float* x  = s ? wm : img;
    const float* w  = s ? ww : iw;
    const float* bb = s ? wb : ib;
    float mu   = g_stats[(s * 16 + b) * 2 + 0];
    float rstd = g_stats[(s * 16 + b) * 2 + 1];
    g_norm[idx] = (x[(size_t)b * C_ * HW_ + chw] - mu) * rstd * w[chw] + bb[chw];
}

// ---------------------------------------------------------------------------
// tf32 helpers
// ---------------------------------------------------------------------------
__device__ __forceinline__ unsigned f2tf32(float f) {
    unsigned r; asm("cvt.rna.tf32.f32 %0, %1;" : "=r"(r) : "f"(f)); return r;
}
__device__ __forceinline__ void mma_tf32(float* c, const unsigned* a, const unsigned* b) {
    asm volatile(
        "mma.sync.aligned.m16n8k8.row.col.f32.tf32.tf32.f32 "
        "{%0,%1,%2,%3}, {%4,%5,%6,%7}, {%8,%9}, {%0,%1,%2,%3};"
        : "+f"(c[0]), "+f"(c[1]), "+f"(c[2]), "+f"(c[3])
        : "r"(a[0]), "r"(a[1]), "r"(a[2]), "r"(a[3]), "r"(b[0]), "r"(b[1]));
}
__device__ __forceinline__ void mma_u(float* c, unsigned a0, unsigned a1, unsigned a2,
                                      unsigned a3, unsigned b0, unsigned b1) {
    asm volatile(
        "mma.sync.aligned.m16n8k8.row.col.f32.tf32.tf32.f32 "
        "{%0,%1,%2,%3}, {%4,%5,%6,%7}, {%8,%9}, {%0,%1,%2,%3};"
        : "+f"(c[0]), "+f"(c[1]), "+f"(c[2]), "+f"(c[3])
        : "r"(a0), "r"(a1), "r"(a2), "r"(a3), "r"(b0), "r"(b1));
}

struct alignas(8) u2 { unsigned hi, lo; };

__device__ __forceinline__ u2 split_tf32(float x) {
    u2 r;
    asm("cvt.rna.tf32.f32 %0, %1;" : "=r"(r.hi) : "f"(x));
    float d = x - __uint_as_float(r.hi);
    asm("cvt.rna.tf32.f32 %0, %1;" : "=r"(r.lo) : "f"(d));
    return r;
}

// ---------------------------------------------------------------------------
// Kernel 3/6: tf32 tensor-core GEMM (single-pass tf32). Block 128x128.
// ---------------------------------------------------------------------------
template <bool TA>
__global__ __launch_bounds__(256)
void gemm_tc(const float* __restrict__ A, const float* __restrict__ Bm,
             float* __restrict__ Cm, const float* __restrict__ bias,
             int M, int N, int K, size_t strideB, size_t strideC) {
    __shared__ unsigned As[2][16][132];
    __shared__ unsigned Bs[2][16][132];
    const float* Bb = Bm + (size_t)blockIdx.z * strideB;
    float* Cb = Cm + (size_t)blockIdx.z * strideC;
    int m0 = blockIdx.y * 128, n0 = blockIdx.x * 128;
    int tid = threadIdx.x, lane = tid & 31, wid = tid >> 5;
    int warpM = wid & 3, warpN = wid >> 2;
    int gi = lane >> 2, li = lane & 3;

    float acc[2][8][4];
#pragma unroll
    for (int mi = 0; mi < 2; mi++)
#pragma unroll
        for (int ni = 0; ni < 8; ni++)
#pragma unroll
            for (int j = 0; j < 4; j++) acc[mi][ni][j] = 0.f;

    const int T = K / 16;
    float4 sa[2], sb[2];

    {
        int k0 = 0;
#pragma unroll
        for (int r = 0; r < 2; r++) {
            int idx = tid + r * 256;
            if (TA) {
                int kl = idx >> 5, mq = idx & 31;
                sa[r] = *(const float4*)&A[(size_t)(k0 + kl) * M + m0 + mq * 4];
            } else {
                int ml = idx >> 2, kq = idx & 3;
                sa[r] = *(const float4*)&A[(size_t)(m0 + ml) * K + k0 + kq * 4];
            }
            int kl = idx >> 5, nq = idx & 31;
            sb[r] = *(const float4*)&Bb[(size_t)(k0 + kl) * N + n0 + nq * 4];
        }
    }
#pragma unroll
    for (int r = 0; r < 2; r++) {
        int idx = tid + r * 256;
        if (TA) {
            int kl = idx >> 5, mq = idx & 31;
            uint4 u = {f2tf32(sa[r].x), f2tf32(sa[r].y), f2tf32(sa[r].z), f2tf32(sa[r].w)};
            *(uint4*)&As[0][kl][mq * 4] = u;
        } else {
            int ml = idx >> 2, kq = idx & 3;
            As[0][kq * 4 + 0][ml] = f2tf32(sa[r].x);
            As[0][kq * 4 + 1][ml] = f2tf32(sa[r].y);
            As[0][kq * 4 + 2][ml] = f2tf32(sa[r].z);
            As[0][kq * 4 + 3][ml] = f2tf32(sa[r].w);
        }
        int kl = idx >> 5, nq = idx & 31;
        uint4 u = {f2tf32(sb[r].x), f2tf32(sb[r].y), f2tf32(sb[r].z), f2tf32(sb[r].w)};
        *(uint4*)&Bs[0][kl][nq * 4] = u;
    }
    __syncthreads();

    for (int t = 0; t < T; t++) {
        int buf = t & 1;
        if (t + 1 < T) {
            int k0 = (t + 1) * 16;
#pragma unroll
            for (int r = 0; r < 2; r++) {
                int idx = tid + r * 256;
                if (TA) {
                    int kl = idx >> 5, mq = idx & 31;
                    sa[r] = *(const float4*)&A[(size_t)(k0 + kl) * M + m0 + mq * 4];
                } else {
                    int ml = idx >> 2, kq = idx & 3;
                    sa[r] = *(const float4*)&A[(size_t)(m0 + ml) * K + k0 + kq * 4];
                }
                int kl = idx >> 5, nq = idx & 31;
                sb[r] = *(const float4*)&Bb[(size_t)(k0 + kl) * N + n0 + nq * 4];
            }
        }
#pragma unroll
        for (int ks = 0; ks < 2; ks++) {
            int k8 = ks * 8;
            unsigned a[2][4], b[8][2];
#pragma unroll
            for (int mi = 0; mi < 2; mi++) {
                int m = warpM * 32 + mi * 16 + gi;
                a[mi][0] = As[buf][k8 + li][m];
                a[mi][1] = As[buf][k8 + li][m + 8];
                a[mi][2] = As[buf][k8 + li + 4][m];
                a[mi][3] = As[buf][k8 + li + 4][m + 8];
            }
#pragma unroll
            for (int ni = 0; ni < 8; ni++) {
                int n = warpN * 64 + ni * 8 + gi;
                b[ni][0] = Bs[buf][k8 + li][n];
                b[ni][1] = Bs[buf][k8 + li + 4][n];
            }
#pragma unroll
            for (int mi = 0; mi < 2; mi++)
#pragma unroll
                for (int ni = 0; ni < 8; ni++)
                    mma_tf32(acc[mi][ni], a[mi], b[ni]);
        }
        if (t + 1 < T) {
            int ob = buf ^ 1;
#pragma unroll
            for (int r = 0; r < 2; r++) {
                int idx = tid + r * 256;
                if (TA) {
                    int kl = idx >> 5, mq = idx & 31;
                    uint4 u = {f2tf32(sa[r].x), f2tf32(sa[r].y), f2tf32(sa[r].z), f2tf32(sa[r].w)};
                    *(uint4*)&As[ob][kl][mq * 4] = u;
                } else {
                    int ml = idx >> 2, kq = idx & 3;
                    As[ob][kq * 4 + 0][ml] = f2tf32(sa[r].x);
                    As[ob][kq * 4 + 1][ml] = f2tf32(sa[r].y);
                    As[ob][kq * 4 + 2][ml] = f2tf32(sa[r].z);
                    As[ob][kq * 4 + 3][ml] = f2tf32(sa[r].w);
                }
                int kl = idx >> 5, nq = idx & 31;
                uint4 u = {f2tf32(sb[r].x), f2tf32(sb[r].y), f2tf32(sb[r].z), f2tf32(sb[r].w)};
                *(uint4*)&Bs[ob][kl][nq * 4] = u;
            }
        }
        __syncthreads();
    }

#pragma unroll
    for (int mi = 0; mi < 2; mi++) {
        int mrow = m0 + warpM * 32 + mi * 16 + gi;
        float bv0 = bias ? bias[mrow] : 0.f;
        float bv1 = bias ? bias[mrow + 8] : 0.f;
#pragma unroll
        for (int ni = 0; ni < 8; ni++) {
            int n = n0 + warpN * 64 + ni * 8 + 2 * li;
            float2 v0 = {acc[mi][ni][0] + bv0, acc[mi][ni][1] + bv0};
            float2 v1 = {acc[mi][ni][2] + bv1, acc[mi][ni][3] + bv1};
            *(float2*)&Cb[(size_t)mrow * N + n] = v0;
            *(float2*)&Cb[(size_t)(mrow + 8) * N + n] = v1;
        }
    }
}

// ---------------------------------------------------------------------------
// Kernel 4: grouped 3x3 conv, smem-tiled
// ---------------------------------------------------------------------------
__global__ __launch_bounds__(256)
void dwconv_kernel(const float* __restrict__ wimg, const float* __restrict__ bimg,
                   const float* __restrict__ wwm,  const float* __restrict__ bwm) {
    __shared__ float sin_[3][HW_];
    __shared__ float sw[81];
    __shared__ float sbias[3];
    int blk = blockIdx.x;
    int g = blk & 511, sb = blk >> 9;
    int s = sb >> 4;
    int tid = threadIdx.x;
    const float* in = g_t + ((size_t)sb * C3_ + g * 3) * HW_;
#pragma unroll
    for (int r = 0; r < 3; r++) {
        int idx = tid + r * 256;
        ((float4*)sin_)[idx] = ((const float4*)in)[idx];
    }
    const float* w = (s ? wwm : wimg) + (size_t)g * 81;
    if (tid < 81) sw[tid] = w[tid];
    if (tid < 3) sbias[tid] = (s ? bwm : bimg)[g * 3 + tid];
    __syncthreads();
    float* outp = g_qkv + ((size_t)sb * C3_ + g * 3) * HW_;
#pragma unroll
    for (int o = 0; o < 3; o++) {
#pragma unroll
        for (int r = 0; r < 4; r++) {
            int hw = tid + r * 256;
            int y = hw >> 5, x = hw & 31;
            float accv = sbias[o];
#pragma unroll
            for (int i = 0; i < 3; i++)
#pragma unroll
                for (int ky = 0; ky < 3; ky++) {
                    int yy = y + ky - 1;
                    if (yy < 0 || yy >= 32) continue;
#pragma unroll
                    for (int kx = 0; kx < 3; kx++) {
                        int xx = x + kx - 1;
                        if (xx < 0 || xx >= 32) continue;
                        accv += sw[o * 27 + i * 9 + ky * 3 + kx] * sin_[i][yy * 32 + xx];
                    }
                }
            outp[(size_t)o * HW_ + hw] = accv;
        }
    }
}

// ---------------------------------------------------------------------------
// Kernel 5: tensor-core cross-attention, tf32x3 precision.
//   One block per (b, head, stream). 256 threads (8 warps).
//   Phase 1: S[k(128)][q(64)] = sum_p K[k][p] Q[q][p]  (contraction 1024)
//   Phase 2: softmax over q per k-row (fp32, smem)
//   Phase 3: out[q][p] = sum_k S[k][q] V[k][p]
// Dynamic smem layout:
//   Ks/Vs : u2[128][35]  (hi/lo tf32, row-major [row][contraction-col])
//   Qs    : u2[32][67]   ([p][q], transposed on staging)
//   S     : float[128][68]
// ---------------------------------------------------------------------------
#define KS_STRIDE 35
#define QS_STRIDE 67
#define S_STRIDE  68
#define SMEM_KS_BYTES  (128 * KS_STRIDE * 8)          // 35840
#define SMEM_QS_BYTES  (32 * QS_STRIDE * 8)           // 17152
#define SMEM_S_OFF     (SMEM_KS_BYTES + SMEM_QS_BYTES) // 52992
#define SMEM_ATTN      (SMEM_S_OFF + 128 * S_STRIDE * 4) // 87808

__global__ __launch_bounds__(256)
void attn_tc_kernel() {
    extern __shared__ char smem_raw[];
    u2*    Ks = (u2*)smem_raw;                        // also Vs in phase 3
    u2*    Qs = (u2*)(smem_raw + SMEM_KS_BYTES);
    float* S  = (float*)(smem_raw + SMEM_S_OFF);

    int bid = blockIdx.x;
    int s = bid & 1, n = (bid >> 1) & 7, b = bid >> 4;
    int tid = threadIdx.x, lane = tid & 31, w = tid >> 5;
    int gi = lane >> 2, li = lane & 3;

    const size_t SB = (size_t)B_ * C3_ * HW_;
    const float* qbase  = g_qkv + (s ? SB : 0) + ((size_t)b * C3_ + n * HC_) * HW_;
    const float* k0base = g_qkv + ((size_t)b * C3_ + C_ + n * HC_) * HW_;
    const float* k1base = k0base + SB;
    const float* v0base = g_qkv + ((size_t)b * C3_ + 2 * C_ + n * HC_) * HW_;
    const float* v1base = v0base + SB;

    // ======== Phase 1: S = K . Q^T ========
    // warp tile 32(k) x 32(q): wM = w&3 (4 M-groups), wN = w>>2 (2 N-groups)
    int wM = w & 3, wN = w >> 2;
    float accS[2][4][4];
#pragma unroll
    for (int mi = 0; mi < 2; mi++)
#pragma unroll
        for (int ni = 0; ni < 4; ni++)
#pragma unroll
            for (int j = 0; j < 4; j++) accS[mi][ni][j] = 0.f;

    for (int pc = 0; pc < 32; pc++) {
        int p0 = pc * 32;
        __syncthreads();
        // stage K chunk [128 rows][32 p], split to hi/lo
#pragma unroll
        for (int i = 0; i < 4; i++) {
            int idx = tid + i * 256;
            int kr = idx >> 3, quad = idx & 7;
            const float* krow = (kr < 64) ? k0base + (size_t)kr * HW_
                                          : k1base + (size_t)(kr - 64) * HW_;
            float4 v = *(const float4*)&krow[p0 + quad * 4];
            u2* dst = &Ks[kr * KS_STRIDE + quad * 4];
            dst[0] = split_tf32(v.x); dst[1] = split_tf32(v.y);
            dst[2] = split_tf32(v.z); dst[3] = split_tf32(v.w);
        }
        // stage Q chunk transposed: Qs[p][q]
#pragma unroll
        for (int i = 0; i < 2; i++) {
            int idx = tid + i * 256;
            int qr = idx >> 3, quad = idx & 7;
            float4 v = *(const float4*)&qbase[(size_t)qr * HW_ + p0 + quad * 4];
            Qs[(quad * 4 + 0) * QS_STRIDE + qr] = split_tf32(v.x);
            Qs[(quad * 4 + 1) * QS_STRIDE + qr] = split_tf32(v.y);
            Qs[(quad * 4 + 2) * QS_STRIDE + qr] = split_tf32(v.z);
            Qs[(quad * 4 + 3) * QS_STRIDE + qr] = split_tf32(v.w);
        }
        __syncthreads();
#pragma unroll
        for (int ks = 0; ks < 4; ks++) {
            int k8 = ks * 8;
            u2 a[2][4], bq[4][2];
#pragma unroll
            for (int mi = 0; mi < 2; mi++) {
                int m = wM * 32 + mi * 16 + gi;
                a[mi][0] = Ks[m * KS_STRIDE + k8 + li];
                a[mi][1] = Ks[(m + 8) * KS_STRIDE + k8 + li];
                a[mi][2] = Ks[m * KS_STRIDE + k8 + li + 4];
                a[mi][3] = Ks[(m + 8) * KS_STRIDE + k8 + li + 4];
            }
#pragma unroll
            for (int ni = 0; ni < 4; ni++) {
                int q = wN * 32 + ni * 8 + gi;
                bq[ni][0] = Qs[(k8 + li) * QS_STRIDE + q];
                bq[ni][1] = Qs[(k8 + li + 4) * QS_STRIDE + q];
            }
#pragma unroll
            for (int mi = 0; mi < 2; mi++)
#pragma unroll
                for (int ni = 0; ni < 4; ni++) {
                    float* c = accS[mi][ni];
                    mma_u(c, a[mi][0].hi, a[mi][1].hi, a[mi][2].hi, a[mi][3].hi,
                          bq[ni][0].hi, bq[ni][1].hi);
                    mma_u(c, a[mi][0].hi, a[mi][1].hi, a[mi][2].hi, a[mi][3].hi,
                          bq[ni][0].lo, bq[ni][1].lo);
                    mma_u(c, a[mi][0].lo, a[mi][1].lo, a[mi][2].lo, a[mi][3].lo,
                          bq[ni][0].hi, bq[ni][1].hi);
                }
        }
    }
    // store S
#pragma unroll
    for (int mi = 0; mi < 2; mi++)
#pragma unroll
        for (int ni = 0; ni < 4; ni++) {
            int m = wM * 32 + mi * 16 + gi;
            int q = wN * 32 + ni * 8 + 2 * li;
            float2 v0 = {accS[mi][ni][0], accS[mi][ni][1]};
            float2 v1 = {accS[mi][ni][2], accS[mi][ni][3]};
            *(float2*)&S[m * S_STRIDE + q] = v0;
            *(float2*)&S[(m + 8) * S_STRIDE + q] = v1;
        }
    __syncthreads();

    // ======== Phase 2: softmax over q per k-row ========
    if (tid < 128) {
        float* row = &S[tid * S_STRIDE];
        float mx = -1e30f;
#pragma unroll 8
        for (int j = 0; j < 64; j++) mx = fmaxf(mx, row[j]);
        float sum = 0.f;
#pragma unroll 8
        for (int j = 0; j < 64; j++) {
            float e = __expf(row[j] - mx);
            row[j] = e; sum += e;
        }
        float inv = 1.f / sum;
#pragma unroll 8
        for (int j = 0; j < 64; j++) row[j] *= inv;
    }

    // ======== Phase 3: out = S^T . V ========
    // chunk of 32 p; within chunk: warp tile 16(q) x 16(p)
    int wM3 = w & 3, wN3 = w >> 2;   // wM3: q-group of 16; wN3: p-group of 16
    float* outbase = g_attn + ((size_t)b * (2 * C_) + n * 128 + s * 64) * HW_;
    for (int pc = 0; pc < 32; pc++) {
        int p0 = pc * 32;
        __syncthreads();
        // stage V chunk [128 k][32 p] hi/lo (aliases Ks region)
#pragma unroll
        for (int i = 0; i < 4; i++) {
            int idx = tid + i * 256;
            int kr = idx >> 3, quad = idx & 7;
            const float* vrow = (kr < 64) ? v0base + (size_t)kr * HW_
                                          : v1base + (size_t)(kr - 64) * HW_;
            float4 v = *(const float4*)&vrow[p0 + quad * 4];
            u2* dst = &Ks[kr * KS_STRIDE + quad * 4];
            dst[0] = split_tf32(v.x); dst[1] = split_tf32(v.y);
            dst[2] = split_tf32(v.z); dst[3] = split_tf32(v.w);
        }
        __syncthreads();
        float acc3[2][4];
#pragma unroll
        for (int ni = 0; ni < 2; ni++)
#pragma unroll
            for (int j = 0; j < 4; j++) acc3[ni][j] = 0.f;
#pragma unroll
        for (int ks = 0; ks < 16; ks++) {
            int k8 = ks * 8;
            int m = wM3 * 16 + gi;
            // A = S^T: A[q][k] = S[k][q], split at load
            u2 a0 = split_tf32(S[(k8 + li) * S_STRIDE + m]);
            u2 a1 = split_tf32(S[(k8 + li) * S_STRIDE + m + 8]);
            u2 a2 = split_tf32(S[(k8 + li + 4) * S_STRIDE + m]);
            u2 a3 = split_tf32(S[(k8 + li + 4) * S_STRIDE + m + 8]);
            u2 bv[2][2];
#pragma unroll
            for (int ni = 0; ni < 2; ni++) {
                int p = wN3 * 16 + ni * 8 + gi;
                bv[ni][0] = Ks[(k8 + li) * KS_STRIDE + p];
                bv[ni][1] = Ks[(k8 + li + 4) * KS_STRIDE + p];
            }
#pragma unroll
            for (int ni = 0; ni < 2; ni++) {
                float* c = acc3[ni];
                mma_u(c, a0.hi, a1.hi, a2.hi, a3.hi, bv[ni][0].hi, bv[ni][1].hi);
                mma_u(c, a0.hi, a1.hi, a2.hi, a3.hi, bv[ni][0].lo, bv[ni][1].lo);
                mma_u(c, a0.lo, a1.lo, a2.lo, a3.lo, bv[ni][0].hi, bv[ni][1].hi);
            }
        }
        // epilogue: rows q, cols p0 + ...
        int qrow = wM3 * 16 + gi;
#pragma unroll
        for (int ni = 0; ni < 2; ni++) {
            int p = p0 + wN3 * 16 + ni * 8 + 2 * li;
            float2 v0 = {acc3[ni][0], acc3[ni][1]};
            float2 v1 = {acc3[ni][2], acc3[ni][3]};
            *(float2*)&outbase[(size_t)qrow * HW_ + p] = v0;
            *(float2*)&outbase[(size_t)(qrow + 8) * HW_ + p] = v1;
        }
    }
}

// ---------------------------------------------------------------------------
extern "C" void kernel_launch(void* const* d_in, const int* in_sizes, int n_in,
                              void* d_out, int out_size) {
    const float* image     = (const float*)d_in[0];
    const float* watermark = (const float*)d_in[1];
    const float* img_ln_w  = (const float*)d_in[2];
    const float* img_ln_b  = (const float*)d_in[3];
    const float* wm_ln_w   = (const float*)d_in[4];
    const float* wm_ln_b   = (const float*)d_in[5];
    const float* img_pw_w  = (const float*)d_in[6];
    const float* img_pw_b  = (const float*)d_in[7];
    const float* img_dw_w  = (const float*)d_in[8];
    const float* img_dw_b  = (const float*)d_in[9];
    const float* wm_pw_w   = (const float*)d_in[10];
    const float* wm_pw_b   = (const float*)d_in[11];
    const float* wm_dw_w   = (const float*)d_in[12];
    const float* wm_dw_b   = (const float*)d_in[13];
    const float* proj      = (const float*)d_in[14];
    float* out = (float*)d_out;

    float *p_norm, *p_t, *p_attn;
    cudaGetSymbolAddress((void**)&p_norm, g_norm);
    cudaGetSymbolAddress((void**)&p_t,    g_t);
    cudaGetSymbolAddress((void**)&p_attn, g_attn);

    static int smem_set = 0;
    if (!smem_set) {
        cudaFuncSetAttribute(attn_tc_kernel,
                             cudaFuncAttributeMaxDynamicSharedMemorySize, SMEM_ATTN);
        smem_set = 1;
    }

    // 1) LayerNorm
    ln_stats<<<32, 512>>>(image, watermark);
    size_t totalN = (size_t)2 * B_ * C_ * HW_;
    ln_apply<<<(unsigned)((totalN + 255) / 256), 256>>>(
        image, watermark, img_ln_w, img_ln_b, wm_ln_w, wm_ln_b);

    // 2) Pointwise 1x1 conv (tf32 tensor-core GEMM), per stream
    dim3 gpw(HW_ / 128, C3_ / 128, B_);
    gemm_tc<false><<<gpw, 256>>>(img_pw_w, p_norm, p_t, img_pw_b,
                                 C3_, HW_, C_, (size_t)C_ * HW_, (size_t)C3_ * HW_);
    gemm_tc<false><<<gpw, 256>>>(wm_pw_w, p_norm + (size_t)B_ * C_ * HW_,
                                 p_t + (size_t)B_ * C3_ * HW_, wm_pw_b,
                                 C3_, HW_, C_, (size_t)C_ * HW_, (size_t)C3_ * HW_);

    // 3) Grouped 3x3 conv (smem-tiled)
    dwconv_kernel<<<32 * 512, 256>>>(img_dw_w, img_dw_b, wm_dw_w, wm_dw_b);

    // 4) Cross-attention (tensor cores, tf32x3)
    attn_tc_kernel<<<B_ * NH_ * 2, 256, SMEM_ATTN>>>();

    // 5) Final projection GEMM
    dim3 gf(HW_ / 128, C_ / 128, B_);
    gemm_tc<true><<<gf, 256>>>(proj, p_attn, out, nullptr,
                               C_, HW_, 2 * C_, (size_t)2 * C_ * HW_, (size_t)C_ * HW_);
}